// round 9
// baseline (speedup 1.0000x reference)
#include <cuda_runtime.h>
#include <cuda_fp16.h>

// out[b,o] = max_k min(x[b,k], w[k,o])  (STE forward == hard max-min)
// x: [B,512] f32 uniform[0,1), w: [512,512] f32, out f32. B = 1024.
//
// R8: one fused kernel, zero L2 gathers in the hot loop.
// Block = 32 b-rows x 64 o-cols. Stage w[:, o-tile] fp32->fp16 into smem
// (64KB, streamed). Per-row candidate lists in smem: tier-1 (x>=0.88,
// ~61) front, tier-2 (x in [0.80,0.88), ~41) back of 160-entry slots;
// slot overflow => exact fp32 row fallback (any-distribution correct).
// Hot loop per candidate per thread: LDS.64 entry + LDS.128 w + 8 HMNMX2
// covering 8 outputs. All latency is smem (29cyc), hidden by ILP.

#define KDIM 512
#define ODIM 512
#define BT   32            // b rows per block
#define OT   64            // o cols per block
#define NT   256           // thread: row r = tid>>3, ogroup og = tid&7 (8 outputs)
#define CROW 160           // candidate slots per row (tier1 front, tier2 back)
#define CUT1 0.88f
#define CUT2 0.80f
#define EPS  1e-3f

#define WS_BYTES (KDIM * OT * 2)                 // 65536: w tile, row k at byte k<<7
#define SMEM_BYTES (WS_BYTES + BT * CROW * 8)    // + 40960 = 106496

__global__ __launch_bounds__(NT, 2)
void maxmin_kernel(const float* __restrict__ x,
                   const float* __restrict__ w,
                   float* __restrict__ out, int B)
{
    extern __shared__ char smem[];
    uint2* cl = reinterpret_cast<uint2*>(smem + WS_BYTES);   // [BT][CROW]
    __shared__ int s_n1[BT], s_n2[BT];

    const int tid = threadIdx.x;
    const int oB  = blockIdx.x * OT;
    const int bB  = blockIdx.y * BT;
    const int r   = tid >> 3;          // row within b-tile
    const int og  = tid & 7;           // output group: outputs [oB+8og, +8)

    if (tid < BT) { s_n1[tid] = 0; s_n2[tid] = 0; }
    __syncthreads();

    // ---- stage w tile fp32 -> fp16 (coalesced stream; no dependent stalls) ----
    {
        uint2* ws2 = reinterpret_cast<uint2*>(smem);
#pragma unroll
        for (int i = 0; i < (KDIM * OT / 4) / NT; i++) {   // 32 iters
            int idx = tid + i * NT;
            int k  = idx >> 4;
            int c4 = idx & 15;
            float4 v = *reinterpret_cast<const float4*>(
                w + (size_t)k * ODIM + oB + c4 * 4);
            __half2 h0 = __floats2half2_rn(v.x, v.y);
            __half2 h1 = __floats2half2_rn(v.z, v.w);
            uint2 pk;
            pk.x = *reinterpret_cast<unsigned*>(&h0);
            pk.y = *reinterpret_cast<unsigned*>(&h1);
            ws2[k * 16 + c4] = pk;     // row k: 16 uint2 = 128B
        }
    }

    // ---- per-row candidate selection (8 threads per row, coalesced 128B) ----
    const bool rvalid = (bB + r) < B;
    if (rvalid) {
        const float4* xr4 =
            reinterpret_cast<const float4*>(x + (size_t)(bB + r) * KDIM);
#pragma unroll
        for (int i = 0; i < 16; i++) {
            float4 v = xr4[i * 8 + og];
            float e[4] = {v.x, v.y, v.z, v.w};
#pragma unroll
            for (int q = 0; q < 4; q++) {
                float xv = e[q];
                if (xv >= CUT2) {
                    int k = (i * 8 + og) * 4 + q;
                    __half   h  = __float2half_rn(xv);
                    __half2  h2 = __halves2half2(h, h);
                    uint2 ent;
                    ent.x = *reinterpret_cast<unsigned*>(&h2);
                    ent.y = (unsigned)(k << 7);          // byte offset of w row
                    if (xv >= CUT1) {
                        int p = atomicAdd(&s_n1[r], 1);
                        if (p < CROW) cl[r * CROW + p] = ent;
                    } else {
                        int p = atomicAdd(&s_n2[r], 1);
                        int pos = CROW - 1 - p;
                        if (pos >= 0) cl[r * CROW + pos] = ent;
                    }
                }
            }
        }
    }
    __syncthreads();

    int c1n = s_n1[r], c2n = s_n2[r];
    const bool ovf = (c1n + c2n > CROW);   // list corrupt -> exact fallback
    if (c1n > CROW) c1n = CROW;
    if (c2n > CROW) c2n = CROW;

    __half2 a0 = __float2half2_rn(0.0f);   // inputs >= 0: 0 is a safe -inf
    __half2 a1 = a0, a2 = a0, a3 = a0;
    const uint2* myl = cl + r * CROW;

    // ---- tier-1 hot loop: all smem ----
    if (rvalid && !ovf) {
#pragma unroll 4
        for (int t = 0; t < c1n; t++) {
            uint2 ent = myl[t];
            uint4 wv = *reinterpret_cast<const uint4*>(smem + ent.y + (og << 4));
            __half2 xv = *reinterpret_cast<__half2*>(&ent.x);
            a0 = __hmax2(a0, __hmin2(xv, *reinterpret_cast<__half2*>(&wv.x)));
            a1 = __hmax2(a1, __hmin2(xv, *reinterpret_cast<__half2*>(&wv.y)));
            a2 = __hmax2(a2, __hmin2(xv, *reinterpret_cast<__half2*>(&wv.z)));
            a3 = __hmax2(a3, __hmin2(xv, *reinterpret_cast<__half2*>(&wv.w)));
        }
    }

    float rr[8];
    rr[0] = __low2float(a0); rr[1] = __high2float(a0);
    rr[2] = __low2float(a1); rr[3] = __high2float(a1);
    rr[4] = __low2float(a2); rr[5] = __high2float(a2);
    rr[6] = __low2float(a3); rr[7] = __high2float(a3);

    // ---- tier-2 extension (P ~ 0.5% per thread) ----
    float rmin = rr[0];
#pragma unroll
    for (int j = 1; j < 8; j++) rmin = fminf(rmin, rr[j]);

    if (rvalid && !ovf && rmin < CUT1 + EPS) {
        for (int t = 0; t < c2n; t++) {
            uint2 ent = myl[CROW - 1 - t];
            uint4 wv = *reinterpret_cast<const uint4*>(smem + ent.y + (og << 4));
            __half2 xv = *reinterpret_cast<__half2*>(&ent.x);
            a0 = __hmax2(a0, __hmin2(xv, *reinterpret_cast<__half2*>(&wv.x)));
            a1 = __hmax2(a1, __hmin2(xv, *reinterpret_cast<__half2*>(&wv.y)));
            a2 = __hmax2(a2, __hmin2(xv, *reinterpret_cast<__half2*>(&wv.z)));
            a3 = __hmax2(a3, __hmin2(xv, *reinterpret_cast<__half2*>(&wv.w)));
        }
        rr[0] = __low2float(a0); rr[1] = __high2float(a0);
        rr[2] = __low2float(a1); rr[3] = __high2float(a1);
        rr[4] = __low2float(a2); rr[5] = __high2float(a2);
        rr[6] = __low2float(a3); rr[7] = __high2float(a3);
    }

    if (!rvalid) return;

    // ---- exact fp32 fallback (essentially never for uniform data) ----
#pragma unroll
    for (int j = 0; j < 8; j++) {
        if (ovf || rr[j] < CUT2 + EPS) {
            int o = oB + og * 8 + j;
            const float* xr = x + (size_t)(bB + r) * KDIM;
            float v = 0.0f;
#pragma unroll 4
            for (int k = 0; k < KDIM; k++)
                v = fmaxf(v, fminf(xr[k], w[(size_t)k * ODIM + o]));
            rr[j] = v;
        }
    }

    float4* op = reinterpret_cast<float4*>(
        out + (size_t)(bB + r) * ODIM + oB + og * 8);
    op[0] = make_float4(rr[0], rr[1], rr[2], rr[3]);
    op[1] = make_float4(rr[4], rr[5], rr[6], rr[7]);
}

extern "C" void kernel_launch(void* const* d_in, const int* in_sizes, int n_in,
                              void* d_out, int out_size)
{
    const float* x = (const float*)d_in[0];   // [B, 512]
    const float* w = (const float*)d_in[1];   // [512, 512]
    float* out = (float*)d_out;

    int B = in_sizes[0] / KDIM;               // 1024

    static int configured = 0;
    if (!configured) {
        cudaFuncSetAttribute(maxmin_kernel,
                             cudaFuncAttributeMaxDynamicSharedMemorySize,
                             SMEM_BYTES);
        configured = 1;
    }

    dim3 grid(ODIM / OT, (B + BT - 1) / BT);  // (8, 32) = 256 blocks
    maxmin_kernel<<<grid, NT, SMEM_BYTES>>>(x, w, out, B);
}